// round 16
// baseline (speedup 1.0000x reference)
#include <cuda_runtime.h>
#include <math.h>
#include <stdint.h>

#define N_NODES 50000
#define N_EDGES 800000
#define DIM     128
#define NQ      8
#define QDIM    768
#define NREL    50
#define NB      8
#define NLAYERS 3
#define ET      128                        // edges per MMA tile (M)
#define KC      32                         // k-chunk
#define NCHUNK  (DIM / KC)                 // 4
#define AS      36                         // padded row stride (floats) for As/Bs
#define PERM_SZ (N_EDGES + NREL * ET)      // 806400 = 6300 * 128

// ---------------- scratch (device globals; no allocs allowed) ----------------
__device__ float g_ha[N_NODES * DIM];
__device__ float g_hb[N_NODES * DIM];
__device__ float g_agg[N_NODES * DIM];
__device__ float g_M[(size_t)PERM_SZ * DIM];   // per-edge messages (perm order)
__device__ float g_Wt[NREL * DIM * DIM];   // per-relation weights, TRANSPOSED [n][k]
__device__ float g_q[NQ * DIM];
__device__ float g_qatt[NQ * NREL];        // sigmoid(dot(q_b, attn_r)) table
__device__ float g_att[N_EDGES];
__device__ int   g_deg[N_NODES];
__device__ float g_dinv[N_NODES];
__device__ int   g_relhist[NREL];
__device__ int   g_pstart[NREL + 1];
__device__ int   g_relcur[NREL];
__device__ int   g_perm[PERM_SZ];
__device__ int   g_dststart[N_NODES];
__device__ int   g_dstcur[N_NODES];
__device__ int   g_dstperm[N_EDGES];       // dst-sorted PERMUTED positions

// ---------------- init ----------------
__global__ void k_degclr() {
    int v = blockIdx.x * blockDim.x + threadIdx.x;
    if (v < N_NODES) { g_deg[v] = 0; g_dstcur[v] = 0; }
}

__global__ void k_permclr() {
    int i = blockIdx.x * blockDim.x + threadIdx.x;
    if (i < PERM_SZ) g_perm[i] = -1;
    if (i < NREL) { g_relhist[i] = 0; g_relcur[i] = 0; }
}

__global__ void k_deghist(const int* dst) {
    int e = blockIdx.x * blockDim.x + threadIdx.x;
    if (e < N_EDGES) atomicAdd(&g_deg[dst[e]], 1);
}

__global__ void k_relhist(const int* etype) {
    int e = blockIdx.x * blockDim.x + threadIdx.x;
    if (e < N_EDGES) atomicAdd(&g_relhist[etype[e]], 1);
}

__global__ void k_reloff() {
    if (blockIdx.x == 0 && threadIdx.x == 0) {
        int run = 0;
        for (int r = 0; r < NREL; r++) {
            g_pstart[r] = run;
            run += ((g_relhist[r] + ET - 1) / ET) * ET;
        }
        g_pstart[NREL] = run;
    }
}

__global__ void k_scatter_rel(const int* etype) {
    int e = blockIdx.x * blockDim.x + threadIdx.x;
    if (e < N_EDGES) {
        int r = etype[e];
        int pos = g_pstart[r] + atomicAdd(&g_relcur[r], 1);
        g_perm[pos] = e;
    }
}

// chunked exclusive scan of g_deg -> g_dststart (single block of 256)
__global__ void k_scan() {
    __shared__ int part[256];
    int tid = threadIdx.x;
    const int CH = (N_NODES + 255) / 256;
    int lo = tid * CH;
    int hi = lo + CH;
    if (hi > N_NODES) hi = N_NODES;
    int s = 0;
    for (int v = lo; v < hi; v++) s += g_deg[v];
    part[tid] = s;
    __syncthreads();
    if (tid == 0) {
        int run = 0;
        for (int i = 0; i < 256; i++) { int t = part[i]; part[i] = run; run += t; }
    }
    __syncthreads();
    int run = part[tid];
    for (int v = lo; v < hi; v++) { g_dststart[v] = run; run += g_deg[v]; }
}

// dst-sorted positions: for each perm slot p with a real edge, file p under dst[e]
__global__ void k_scatter_dst(const int* dst) {
    int p = blockIdx.x * blockDim.x + threadIdx.x;
    if (p < PERM_SZ) {
        int e = g_perm[p];
        if (e >= 0) {
            int d = dst[e];
            int pos = g_dststart[d] + atomicAdd(&g_dstcur[d], 1);
            g_dstperm[pos] = p;
        }
    }
}

__global__ void k_deginv() {
    int v = blockIdx.x * blockDim.x + threadIdx.x;
    if (v < N_NODES) {
        int d = g_deg[v];
        if (d < 1) d = 1;
        g_dinv[v] = __fdividef(1.0f, (float)d);
    }
}

// ---------------- query projection ----------------
__global__ void k_qproj(const float* qe, const float* w, const float* b) {
    int qi = blockIdx.x;
    int j = threadIdx.x;
    float acc = b[j];
    for (int k = 0; k < QDIM; k++) acc += qe[qi * QDIM + k] * w[k * DIM + j];
    g_q[qi * DIM + j] = acc;
}

// ---------------- (batch, rel) attention table ----------------
__global__ void k_qatt(const float* attn_l) {
    int b = blockIdx.x;
    int r = threadIdx.x;
    if (r >= NREL) return;
    float s = 0.f;
    for (int k = 0; k < DIM; k++) s += g_q[b * DIM + k] * attn_l[r * DIM + k];
    float ex = __expf(-s);
    g_qatt[b * NREL + r] = __fdividef(1.0f, 1.0f + ex);
}

__global__ void k_att(const int* ebatch, const int* etype) {
    int e = blockIdx.x * blockDim.x + threadIdx.x;
    if (e >= N_EDGES) return;
    g_att[e] = g_qatt[ebatch[e] * NREL + etype[e]];
}

// ---------------- per-relation composed weight, TRANSPOSED [r][n][k] ----------------
__global__ void k_relW(const float* bases_l, const float* comp_l) {
    int r = blockIdx.x;
    float c0 = comp_l[r * NB + 0], c1 = comp_l[r * NB + 1];
    float c2 = comp_l[r * NB + 2], c3 = comp_l[r * NB + 3];
    float c4 = comp_l[r * NB + 4], c5 = comp_l[r * NB + 5];
    float c6 = comp_l[r * NB + 6], c7 = comp_l[r * NB + 7];
    for (int idx = threadIdx.x; idx < DIM * DIM; idx += blockDim.x) {
        float s0 = c0 * bases_l[0 * DIM * DIM + idx]
                 + c1 * bases_l[1 * DIM * DIM + idx]
                 + c2 * bases_l[2 * DIM * DIM + idx]
                 + c3 * bases_l[3 * DIM * DIM + idx]
                 + c4 * bases_l[4 * DIM * DIM + idx]
                 + c5 * bases_l[5 * DIM * DIM + idx]
                 + c6 * bases_l[6 * DIM * DIM + idx]
                 + c7 * bases_l[7 * DIM * DIM + idx];
        int k = idx >> 7;
        int n = idx & 127;
        g_Wt[r * DIM * DIM + n * DIM + k] = s0;
    }
}

// ============ mma.sync tf32 edge-message GEMM ============
// CTA = 128 edges (one relation) x 128 cols; 8 warps, warp w owns rows 16w..16w+15.
// Messages stored dense to g_M in perm order (no atomics).
#define MMA_T(n) { \
    uint32_t b0 = __float_as_uint(Bs[(n * 8 + ln4) * AS + ksoff + kq]); \
    uint32_t b1 = __float_as_uint(Bs[(n * 8 + ln4) * AS + ksoff + kq + 4]); \
    asm volatile("mma.sync.aligned.m16n8k8.row.col.f32.tf32.tf32.f32 " \
        "{%0,%1,%2,%3}, {%4,%5,%6,%7}, {%8,%9}, {%0,%1,%2,%3};" \
        : "+f"(acc##n.x), "+f"(acc##n.y), "+f"(acc##n.z), "+f"(acc##n.w) \
        : "r"(a0), "r"(a1), "r"(a2), "r"(a3), "r"(b0), "r"(b1)); }

#define KSTEP { \
    uint32_t a0 = __float_as_uint(As[ar0 + ksoff + kq]); \
    uint32_t a1 = __float_as_uint(As[ar8 + ksoff + kq]); \
    uint32_t a2 = __float_as_uint(As[ar0 + ksoff + kq + 4]); \
    uint32_t a3 = __float_as_uint(As[ar8 + ksoff + kq + 4]); \
    MMA_T(0)  MMA_T(1)  MMA_T(2)  MMA_T(3) \
    MMA_T(4)  MMA_T(5)  MMA_T(6)  MMA_T(7) \
    MMA_T(8)  MMA_T(9)  MMA_T(10) MMA_T(11) \
    MMA_T(12) MMA_T(13) MMA_T(14) MMA_T(15) }

// direct fragment store: rows mrow0 (=.x,.y) and mrow0+8 (=.z,.w), cols 8n+2*(lane&3)
#define EST(n) { \
    float* mp = g_M + (size_t)mrow0 * DIM + 8 * (n) + 2 * (lane & 3); \
    *(float2*)mp = make_float2(acc##n.x, acc##n.y); \
    *(float2*)(mp + 8 * DIM) = make_float2(acc##n.z, acc##n.w); }

__global__ void __launch_bounds__(256) k_emsg(const float* h, const int* src) {
    __shared__ float As[ET * AS];     // 18 KB staged A (att-scaled fp32)
    __shared__ float Bs[ET * AS];     // 18 KB staged W^T (fp32)
    __shared__ int   s_src[ET];
    __shared__ float s_att[ET];
    __shared__ int   s_rel;

    int tid = threadIdx.x;
    int wid = tid >> 5;
    int lane = tid & 31;
    int tilebase = blockIdx.x * ET;

    if (tid == 0) {
        int r = 0;
        while (r < NREL && !(tilebase >= g_pstart[r] && tilebase < g_pstart[r + 1])) r++;
        s_rel = r;
    }
    if (tid < ET) {
        int e = g_perm[tilebase + tid];
        s_src[tid] = (e >= 0) ? src[e] : 0;
        s_att[tid] = (e >= 0) ? g_att[e] : 0.f;
    }
    __syncthreads();
    if (s_rel >= NREL) return;

    const float* Wt = g_Wt + s_rel * DIM * DIM;

    float4 z4 = make_float4(0.f, 0.f, 0.f, 0.f);
    float4 acc0 = z4, acc1 = z4, acc2 = z4, acc3 = z4;
    float4 acc4 = z4, acc5 = z4, acc6 = z4, acc7 = z4;
    float4 acc8 = z4, acc9 = z4, acc10 = z4, acc11 = z4;
    float4 acc12 = z4, acc13 = z4, acc14 = z4, acc15 = z4;

    int srow = tid >> 1;
    int sh = tid & 1;
    int ln4 = lane >> 2;
    int kq = lane & 3;
    int ar0 = (16 * wid + ln4) * AS;
    int ar8 = ar0 + 8 * AS;

    for (int kc = 0; kc < NCHUNK; kc++) {
        {   // stage A: raw fp32, att-scaled, float4 stores
            const float4* gp = (const float4*)(h + (size_t)s_src[srow] * DIM + kc * KC + sh * 16);
            float a = s_att[srow];
            float4* ap = (float4*)(As + srow * AS + sh * 16);
            float4 v0 = gp[0], v1 = gp[1], v2 = gp[2], v3 = gp[3];
            ap[0] = make_float4(v0.x * a, v0.y * a, v0.z * a, v0.w * a);
            ap[1] = make_float4(v1.x * a, v1.y * a, v1.z * a, v1.w * a);
            ap[2] = make_float4(v2.x * a, v2.y * a, v2.z * a, v2.w * a);
            ap[3] = make_float4(v3.x * a, v3.y * a, v3.z * a, v3.w * a);
        }
        {   // stage B: raw fp32 copy
            const float4* gp = (const float4*)(Wt + (size_t)srow * DIM + kc * KC + sh * 16);
            float4* bp = (float4*)(Bs + srow * AS + sh * 16);
            bp[0] = gp[0];
            bp[1] = gp[1];
            bp[2] = gp[2];
            bp[3] = gp[3];
        }
        __syncthreads();

        for (int ks = 0; ks < 4; ks++) {
            int ksoff = ks * 8;
            KSTEP
        }
        __syncthreads();
    }

    int mrow0 = tilebase + 16 * wid + ln4;
    EST(0)  EST(1)  EST(2)  EST(3)
    EST(4)  EST(5)  EST(6)  EST(7)
    EST(8)  EST(9)  EST(10) EST(11)
    EST(12) EST(13) EST(14) EST(15)
}

// ---------------- aggregation: g_agg[v] = sum over edges of g_M rows ----------------
__global__ void k_agg() {
    int warp = (blockIdx.x * blockDim.x + threadIdx.x) >> 5;
    int lane = threadIdx.x & 31;
    if (warp >= N_NODES) return;
    float ax = 0.f, ay = 0.f, az = 0.f, aw = 0.f;
    int s = g_dststart[warp];
    int d = g_deg[warp];
    for (int i = 0; i < d; i++) {
        int p = g_dstperm[s + i];
        float4 m = *(const float4*)&g_M[(size_t)p * DIM + lane * 4];
        ax += m.x; ay += m.y; az += m.z; aw += m.w;
    }
    *(float4*)&g_agg[(size_t)warp * DIM + lane * 4] = make_float4(ax, ay, az, aw);
}

// ---------------- scalar fp32 tiled node GEMM (R13-proven) ----------------
#define DECL_ACC32 \
    float c00=0.f,c01=0.f,c02=0.f,c03=0.f,c04=0.f,c05=0.f,c06=0.f,c07=0.f; \
    float c10=0.f,c11=0.f,c12=0.f,c13=0.f,c14=0.f,c15=0.f,c16=0.f,c17=0.f; \
    float c20=0.f,c21=0.f,c22=0.f,c23=0.f,c24=0.f,c25=0.f,c26=0.f,c27=0.f; \
    float c30=0.f,c31=0.f,c32=0.f,c33=0.f,c34=0.f,c35=0.f,c36=0.f,c37=0.f;

#define ROWFMA(m) \
    c##m##0 += a##m * b0; c##m##1 += a##m * b1; c##m##2 += a##m * b2; c##m##3 += a##m * b3; \
    c##m##4 += a##m * b4; c##m##5 += a##m * b5; c##m##6 += a##m * b6; c##m##7 += a##m * b7;

#define NT      64
#define NATS    68

#define NROWOUT(m) \
    { int row2 = base + 4 * rg + m; \
      if (row2 < N_NODES) { \
          float s0 = c##m##0 + bx0, s1 = c##m##1 + bx1, s2 = c##m##2 + bx2, s3 = c##m##3 + bx3; \
          float s4 = c##m##4 + bx4, s5 = c##m##5 + bx5, s6 = c##m##6 + bx6, s7 = c##m##7 + bx7; \
          if (mode != 0) { \
              float di = g_dinv[row2]; \
              const float* gp = g_agg + (size_t)row2 * DIM + 8 * cg; \
              s0 += gp[0] * di; s1 += gp[1] * di; s2 += gp[2] * di; s3 += gp[3] * di; \
              s4 += gp[4] * di; s5 += gp[5] * di; s6 += gp[6] * di; s7 += gp[7] * di; \
          } \
          if (mode == 1) { \
              s0 = fmaxf(s0, 0.f); s1 = fmaxf(s1, 0.f); s2 = fmaxf(s2, 0.f); s3 = fmaxf(s3, 0.f); \
              s4 = fmaxf(s4, 0.f); s5 = fmaxf(s5, 0.f); s6 = fmaxf(s6, 0.f); s7 = fmaxf(s7, 0.f); \
          } \
          float* dp = dest + (size_t)row2 * DIM + 8 * cg; \
          *(float4*)dp = make_float4(s0, s1, s2, s3); \
          *(float4*)(dp + 4) = make_float4(s4, s5, s6, s7); } }

__global__ void k_ngemm(const float* A, const int* gidx, const float* Bw,
                        const float* bias, float* dest, int mode) {
    __shared__ float Bsn[KC * DIM];
    __shared__ float Atsn[KC * NATS];
    __shared__ int s_row[NT];

    int tid = threadIdx.x;
    int base = blockIdx.x * NT;

    if (tid < NT) {
        int r = base + tid;
        int rr = (r < N_NODES) ? r : (N_NODES - 1);
        s_row[tid] = gidx ? gidx[rr] : rr;
    }
    __syncthreads();

    int cg = tid & 15;
    int rg = tid >> 4;
    int arow = tid & 63;
    int aq = tid >> 6;
    DECL_ACC32

    for (int kc = 0; kc < NCHUNK; kc++) {
        for (int i = 0; i < 4; i++) {
            int idx = i * 256 + tid;
            ((float4*)Bsn)[idx] = ((const float4*)(Bw + kc * KC * DIM))[idx];
        }
        {
            const float* hp = A + (size_t)s_row[arow] * DIM + kc * KC;
            float4 v0 = *(const float4*)(hp + 4 * aq);
            float4 v1 = *(const float4*)(hp + 16 + 4 * aq);
            Atsn[(4 * aq + 0) * NATS + arow] = v0.x;
            Atsn[(4 * aq + 1) * NATS + arow] = v0.y;
            Atsn[(4 * aq + 2) * NATS + arow] = v0.z;
            Atsn[(4 * aq + 3) * NATS + arow] = v0.w;
            Atsn[(16 + 4 * aq + 0) * NATS + arow] = v1.x;
            Atsn[(16 + 4 * aq + 1) * NATS + arow] = v1.y;
            Atsn[(16 + 4 * aq + 2) * NATS + arow] = v1.z;
            Atsn[(16 + 4 * aq + 3) * NATS + arow] = v1.w;
        }
        __syncthreads();

        for (int k = 0; k < KC; k++) {
            float4 av  = *(const float4*)&Atsn[k * NATS + 4 * rg];
            float4 bv0 = *(const float4*)&Bsn[k * DIM + 8 * cg];
            float4 bv1 = *(const float4*)&Bsn[k * DIM + 8 * cg + 4];
            float a0 = av.x, a1 = av.y, a2 = av.z, a3 = av.w;
            float b0 = bv0.x, b1 = bv0.y, b2 = bv0.z, b3 = bv0.w;
            float b4 = bv1.x, b5 = bv1.y, b6 = bv1.z, b7 = bv1.w;
            ROWFMA(0) ROWFMA(1) ROWFMA(2) ROWFMA(3)
        }
        __syncthreads();
    }

    float4 bv0 = *(const float4*)(bias + 8 * cg);
    float4 bv1 = *(const float4*)(bias + 8 * cg + 4);
    float bx0 = bv0.x, bx1 = bv0.y, bx2 = bv0.z, bx3 = bv0.w;
    float bx4 = bv1.x, bx5 = bv1.y, bx6 = bv1.z, bx7 = bv1.w;

    NROWOUT(0) NROWOUT(1) NROWOUT(2) NROWOUT(3)
}

// ---------------- launch ----------------
extern "C" void kernel_launch(void* const* d_in, const int* in_sizes, int n_in,
                              void* d_out, int out_size) {
    const int*   x          = (const int*)d_in[0];
    const int*   edge_index = (const int*)d_in[1];
    const int*   edge_type  = (const int*)d_in[2];
    const float* query_emb  = (const float*)d_in[3];
    // d_in[4] = x_batch (unused by reference)
    const int*   edge_batch = (const int*)d_in[5];
    const float* embed_w    = (const float*)d_in[6];
    const float* ilw        = (const float*)d_in[7];
    const float* ilb        = (const float*)d_in[8];
    const float* qpw        = (const float*)d_in[9];
    const float* qpb        = (const float*)d_in[10];
    const float* bases      = (const float*)d_in[11];
    const float* comp       = (const float*)d_in[12];
    const float* rootw      = (const float*)d_in[13];
    const float* lbias      = (const float*)d_in[14];
    const float* relattn    = (const float*)d_in[15];
    float* out = (float*)d_out;

    const int* src = edge_index;
    const int* dst = edge_index + N_EDGES;

    const int NODEB  = (N_NODES + 255) / 256;
    const int EBLK   = (N_EDGES + 255) / 256;
    const int PBLK   = (PERM_SZ + 255) / 256;
    const int ETILES = PERM_SZ / ET;                   // 6300
    const int NTILES = (N_NODES + NT - 1) / NT;        // 782
    const int AGGB   = (N_NODES * 32 + 255) / 256;

    float* ha = nullptr; float* hb = nullptr;
    cudaGetSymbolAddress((void**)&ha, g_ha);
    cudaGetSymbolAddress((void**)&hb, g_hb);

    // launch #4 = hinit k_ngemm (ncu capture slot)
    k_qproj<<<NQ, DIM>>>(query_emb, qpw, qpb);
    k_degclr<<<NODEB, 256>>>();
    k_permclr<<<PBLK, 256>>>();
    k_ngemm<<<NTILES, 256>>>(embed_w, x, ilw, ilb, ha, 0);
    k_deghist<<<EBLK, 256>>>(dst);
    k_relhist<<<EBLK, 256>>>(edge_type);
    k_reloff<<<1, 32>>>();
    k_scatter_rel<<<EBLK, 256>>>(edge_type);
    k_scan<<<1, 256>>>();
    k_scatter_dst<<<PBLK, 256>>>(dst);
    k_deginv<<<NODEB, 256>>>();

    float* cur = ha;
    float* nxt = hb;
    for (int l = 0; l < NLAYERS; l++) {
        k_relW<<<NREL, 256>>>(bases + (size_t)l * NB * DIM * DIM,
                              comp + (size_t)l * NREL * NB);
        k_qatt<<<NQ, 64>>>(relattn + (size_t)l * NREL * DIM);
        k_att<<<EBLK, 256>>>(edge_batch, edge_type);
        k_emsg<<<ETILES, 256>>>(cur, src);
        k_agg<<<AGGB, 256>>>();
        float* dest = (l == NLAYERS - 1) ? out : nxt;
        int mode = (l == NLAYERS - 1) ? 2 : 1;
        k_ngemm<<<NTILES, 256>>>(cur, nullptr, rootw + (size_t)l * DIM * DIM,
                                 lbias + (size_t)l * DIM, dest, mode);
        float* t = cur; cur = nxt; nxt = t;
    }
}

// round 17
// speedup vs baseline: 1.1287x; 1.1287x over previous
#include <cuda_runtime.h>
#include <cuda_bf16.h>
#include <math.h>
#include <stdint.h>

#define N_NODES 50000
#define N_EDGES 800000
#define DIM     128
#define NQ      8
#define QDIM    768
#define NREL    50
#define NB      8
#define NLAYERS 3
#define ET      128                        // edges per MMA tile (M)
#define KC      32                         // k-chunk
#define NCHUNK  (DIM / KC)                 // 4
#define AS2     20                         // u32 row stride for packed bf16x2 tiles
#define DSS     36                         // float row stride for epilogue staging
#define PERM_SZ (N_EDGES + NREL * ET)      // 806400 = 6300 * 128

// ---------------- scratch (device globals; no allocs allowed) ----------------
__device__ float g_ha[N_NODES * DIM];
__device__ float g_hb[N_NODES * DIM];
__device__ float g_agg[N_NODES * DIM];
__device__ float g_Wt[NREL * DIM * DIM];   // per-relation weights, TRANSPOSED [n][k]
__device__ float g_q[NQ * DIM];
__device__ float g_qatt[NQ * NREL];        // sigmoid(dot(q_b, attn_r)) table
__device__ float g_att[N_EDGES];
__device__ int   g_deg[N_NODES];
__device__ float g_dinv[N_NODES];
__device__ int   g_relhist[NREL];
__device__ int   g_pstart[NREL + 1];
__device__ int   g_relcur[NREL];
__device__ int   g_perm[PERM_SZ];

// ---------------- helpers ----------------
static __device__ __forceinline__ uint32_t bpack(float lo, float hi) {
    uint32_t u;
    asm("cvt.rn.bf16x2.f32 %0, %1, %2;" : "=r"(u) : "f"(hi), "f"(lo));
    return u;
}

// ---------------- init ----------------
__global__ void k_degclr() {
    int v = blockIdx.x * blockDim.x + threadIdx.x;
    if (v < N_NODES) g_deg[v] = 0;
}

__global__ void k_permclr() {
    int i = blockIdx.x * blockDim.x + threadIdx.x;
    if (i < PERM_SZ) g_perm[i] = -1;
    if (i < NREL) { g_relhist[i] = 0; g_relcur[i] = 0; }
}

__global__ void k_deghist(const int* dst) {
    int e = blockIdx.x * blockDim.x + threadIdx.x;
    if (e < N_EDGES) atomicAdd(&g_deg[dst[e]], 1);
}

__global__ void k_relhist(const int* etype) {
    int e = blockIdx.x * blockDim.x + threadIdx.x;
    if (e < N_EDGES) atomicAdd(&g_relhist[etype[e]], 1);
}

__global__ void k_reloff() {
    if (blockIdx.x == 0 && threadIdx.x == 0) {
        int run = 0;
        for (int r = 0; r < NREL; r++) {
            g_pstart[r] = run;
            run += ((g_relhist[r] + ET - 1) / ET) * ET;
        }
        g_pstart[NREL] = run;
    }
}

__global__ void k_scatter_rel(const int* etype) {
    int e = blockIdx.x * blockDim.x + threadIdx.x;
    if (e < N_EDGES) {
        int r = etype[e];
        int pos = g_pstart[r] + atomicAdd(&g_relcur[r], 1);
        g_perm[pos] = e;
    }
}

__global__ void k_deginv() {
    int v = blockIdx.x * blockDim.x + threadIdx.x;
    if (v < N_NODES) {
        int d = g_deg[v];
        if (d < 1) d = 1;
        g_dinv[v] = __fdividef(1.0f, (float)d);
    }
}

// ---------------- query projection ----------------
__global__ void k_qproj(const float* qe, const float* w, const float* b) {
    int qi = blockIdx.x;
    int j = threadIdx.x;
    float acc = b[j];
    for (int k = 0; k < QDIM; k++) acc += qe[qi * QDIM + k] * w[k * DIM + j];
    g_q[qi * DIM + j] = acc;
}

// ---------------- (batch, rel) attention table ----------------
__global__ void k_qatt(const float* attn_l) {
    int b = blockIdx.x;
    int r = threadIdx.x;
    if (r >= NREL) return;
    float s = 0.f;
    for (int k = 0; k < DIM; k++) s += g_q[b * DIM + k] * attn_l[r * DIM + k];
    float ex = __expf(-s);
    g_qatt[b * NREL + r] = __fdividef(1.0f, 1.0f + ex);
}

__global__ void k_att(const int* ebatch, const int* etype) {
    int e = blockIdx.x * blockDim.x + threadIdx.x;
    if (e >= N_EDGES) return;
    g_att[e] = g_qatt[ebatch[e] * NREL + etype[e]];
}

// ---------------- per-relation composed weight, TRANSPOSED [r][n][k] ----------------
__global__ void k_relW(const float* bases_l, const float* comp_l) {
    int r = blockIdx.x;
    float c0 = comp_l[r * NB + 0], c1 = comp_l[r * NB + 1];
    float c2 = comp_l[r * NB + 2], c3 = comp_l[r * NB + 3];
    float c4 = comp_l[r * NB + 4], c5 = comp_l[r * NB + 5];
    float c6 = comp_l[r * NB + 6], c7 = comp_l[r * NB + 7];
    for (int idx = threadIdx.x; idx < DIM * DIM; idx += blockDim.x) {
        float s0 = c0 * bases_l[0 * DIM * DIM + idx]
                 + c1 * bases_l[1 * DIM * DIM + idx]
                 + c2 * bases_l[2 * DIM * DIM + idx]
                 + c3 * bases_l[3 * DIM * DIM + idx]
                 + c4 * bases_l[4 * DIM * DIM + idx]
                 + c5 * bases_l[5 * DIM * DIM + idx]
                 + c6 * bases_l[6 * DIM * DIM + idx]
                 + c7 * bases_l[7 * DIM * DIM + idx];
        int k = idx >> 7;
        int n = idx & 127;
        g_Wt[r * DIM * DIM + n * DIM + k] = s0;
    }
}

// ---------------- clear aggregation buffer ----------------
__global__ void k_aggclr() {
    int idx = blockIdx.x * blockDim.x + threadIdx.x;
    if (idx < N_NODES * DIM) g_agg[idx] = 0.f;
}

// ============ mma.sync bf16 m16n8k16 edge-message GEMM ============
// CTA = 128 edges (one relation) x 128 cols; 8 warps, warp w owns rows 16w..16w+15.
// Inputs packed bf16x2 in smem; fp32 accumulate; coalesced atomic epilogue.
#define MMA_B(n) { \
    uint32_t b0 = Bs32[(n * 8 + ln4) * AS2 + ksoff + kq]; \
    uint32_t b1 = Bs32[(n * 8 + ln4) * AS2 + ksoff + kq + 4]; \
    asm volatile("mma.sync.aligned.m16n8k16.row.col.f32.bf16.bf16.f32 " \
        "{%0,%1,%2,%3}, {%4,%5,%6,%7}, {%8,%9}, {%0,%1,%2,%3};" \
        : "+f"(acc##n.x), "+f"(acc##n.y), "+f"(acc##n.z), "+f"(acc##n.w) \
        : "r"(a0), "r"(a1), "r"(a2), "r"(a3), "r"(b0), "r"(b1)); }

#define KSTEP16 { \
    uint32_t a0 = As32[ar0 + ksoff + kq]; \
    uint32_t a1 = As32[ar8 + ksoff + kq]; \
    uint32_t a2 = As32[ar0 + ksoff + kq + 4]; \
    uint32_t a3 = As32[ar8 + ksoff + kq + 4]; \
    MMA_B(0)  MMA_B(1)  MMA_B(2)  MMA_B(3) \
    MMA_B(4)  MMA_B(5)  MMA_B(6)  MMA_B(7) \
    MMA_B(8)  MMA_B(9)  MMA_B(10) MMA_B(11) \
    MMA_B(12) MMA_B(13) MMA_B(14) MMA_B(15) }

#define EPI_TILE(j, n) { \
    int lc = (j) * 8 + 2 * (lane & 3); \
    Ds[dr0 + lc]     = acc##n.x; \
    Ds[dr0 + lc + 1] = acc##n.y; \
    Ds[dr8 + lc]     = acc##n.z; \
    Ds[dr8 + lc + 1] = acc##n.w; }

#define EPI_CB_E(cb, n0, n1, n2, n3) { \
    EPI_TILE(0, n0) EPI_TILE(1, n1) EPI_TILE(2, n2) EPI_TILE(3, n3) \
    __syncwarp(); \
    for (int i = 0; i < 16; i++) { \
        int r2 = 16 * wid + i; \
        int e = s_eid[r2]; \
        if (e >= 0) \
            atomicAdd(&g_agg[(size_t)s_dst[r2] * DIM + (cb) * 32 + lane], \
                      Ds[r2 * DSS + lane]); \
    } \
    __syncwarp(); }

__global__ void __launch_bounds__(256) k_emsg(const float* h, const int* src, const int* dst) {
    __shared__ uint32_t smraw[2 * ET * AS2];   // 20 KB: As32 | Bs32; Ds overlays
    __shared__ int   s_eid[ET];
    __shared__ int   s_src[ET];
    __shared__ int   s_dst[ET];
    __shared__ float s_att[ET];
    __shared__ int   s_rel;

    uint32_t* As32 = smraw;
    uint32_t* Bs32 = smraw + ET * AS2;

    int tid = threadIdx.x;
    int wid = tid >> 5;
    int lane = tid & 31;
    int tilebase = blockIdx.x * ET;

    if (tid == 0) {
        int r = 0;
        while (r < NREL && !(tilebase >= g_pstart[r] && tilebase < g_pstart[r + 1])) r++;
        s_rel = r;
    }
    if (tid < ET) {
        int e = g_perm[tilebase + tid];
        s_eid[tid] = e;
        s_src[tid] = (e >= 0) ? src[e] : 0;
        s_dst[tid] = (e >= 0) ? dst[e] : 0;
        s_att[tid] = (e >= 0) ? g_att[e] : 0.f;
    }
    __syncthreads();
    if (s_rel >= NREL) return;

    const float* Wt = g_Wt + s_rel * DIM * DIM;

    float4 z4 = make_float4(0.f, 0.f, 0.f, 0.f);
    float4 acc0 = z4, acc1 = z4, acc2 = z4, acc3 = z4;
    float4 acc4 = z4, acc5 = z4, acc6 = z4, acc7 = z4;
    float4 acc8 = z4, acc9 = z4, acc10 = z4, acc11 = z4;
    float4 acc12 = z4, acc13 = z4, acc14 = z4, acc15 = z4;

    int srow = tid >> 1;
    int sh = tid & 1;
    int ln4 = lane >> 2;
    int kq = lane & 3;
    int ar0 = (16 * wid + ln4) * AS2;
    int ar8 = ar0 + 8 * AS2;

    for (int kc = 0; kc < NCHUNK; kc++) {
        {   // stage A: att-scaled, packed bf16x2, 2 uint4 stores
            const float4* gp = (const float4*)(h + (size_t)s_src[srow] * DIM + kc * KC + sh * 16);
            float a = s_att[srow];
            float4 v0 = gp[0], v1 = gp[1], v2 = gp[2], v3 = gp[3];
            uint4* ap = (uint4*)(As32 + srow * AS2 + sh * 8);
            ap[0] = make_uint4(bpack(v0.x * a, v0.y * a), bpack(v0.z * a, v0.w * a),
                               bpack(v1.x * a, v1.y * a), bpack(v1.z * a, v1.w * a));
            ap[1] = make_uint4(bpack(v2.x * a, v2.y * a), bpack(v2.z * a, v2.w * a),
                               bpack(v3.x * a, v3.y * a), bpack(v3.z * a, v3.w * a));
        }
        {   // stage B: packed bf16x2
            const float4* gp = (const float4*)(Wt + (size_t)srow * DIM + kc * KC + sh * 16);
            float4 v0 = gp[0], v1 = gp[1], v2 = gp[2], v3 = gp[3];
            uint4* bp = (uint4*)(Bs32 + srow * AS2 + sh * 8);
            bp[0] = make_uint4(bpack(v0.x, v0.y), bpack(v0.z, v0.w),
                               bpack(v1.x, v1.y), bpack(v1.z, v1.w));
            bp[1] = make_uint4(bpack(v2.x, v2.y), bpack(v2.z, v2.w),
                               bpack(v3.x, v3.y), bpack(v3.z, v3.w));
        }
        __syncthreads();

        {   int ksoff = 0; KSTEP16 }
        {   int ksoff = 8; KSTEP16 }
        __syncthreads();
    }

    // epilogue: re-coalesce through smem (overlay), then coalesced atomics
    float* Ds = (float*)smraw;
    int dr0 = (16 * wid + ln4) * DSS;
    int dr8 = dr0 + 8 * DSS;
    EPI_CB_E(0, 0, 1, 2, 3)
    EPI_CB_E(1, 4, 5, 6, 7)
    EPI_CB_E(2, 8, 9, 10, 11)
    EPI_CB_E(3, 12, 13, 14, 15)
}

// ---------------- scalar fp32 tiled node GEMM (R13-proven) ----------------
#define DECL_ACC32 \
    float c00=0.f,c01=0.f,c02=0.f,c03=0.f,c04=0.f,c05=0.f,c06=0.f,c07=0.f; \
    float c10=0.f,c11=0.f,c12=0.f,c13=0.f,c14=0.f,c15=0.f,c16=0.f,c17=0.f; \
    float c20=0.f,c21=0.f,c22=0.f,c23=0.f,c24=0.f,c25=0.f,c26=0.f,c27=0.f; \
    float c30=0.f,c31=0.f,c32=0.f,c33=0.f,c34=0.f,c35=0.f,c36=0.f,c37=0.f;

#define ROWFMA(m) \
    c##m##0 += a##m * b0; c##m##1 += a##m * b1; c##m##2 += a##m * b2; c##m##3 += a##m * b3; \
    c##m##4 += a##m * b4; c##m##5 += a##m * b5; c##m##6 += a##m * b6; c##m##7 += a##m * b7;

#define NT      64
#define NATS    68

#define NROWOUT(m) \
    { int row2 = base + 4 * rg + m; \
      if (row2 < N_NODES) { \
          float s0 = c##m##0 + bx0, s1 = c##m##1 + bx1, s2 = c##m##2 + bx2, s3 = c##m##3 + bx3; \
          float s4 = c##m##4 + bx4, s5 = c##m##5 + bx5, s6 = c##m##6 + bx6, s7 = c##m##7 + bx7; \
          if (mode != 0) { \
              float di = g_dinv[row2]; \
              const float* gp = g_agg + (size_t)row2 * DIM + 8 * cg; \
              s0 += gp[0] * di; s1 += gp[1] * di; s2 += gp[2] * di; s3 += gp[3] * di; \
              s4 += gp[4] * di; s5 += gp[5] * di; s6 += gp[6] * di; s7 += gp[7] * di; \
          } \
          if (mode == 1) { \
              s0 = fmaxf(s0, 0.f); s1 = fmaxf(s1, 0.f); s2 = fmaxf(s2, 0.f); s3 = fmaxf(s3, 0.f); \
              s4 = fmaxf(s4, 0.f); s5 = fmaxf(s5, 0.f); s6 = fmaxf(s6, 0.f); s7 = fmaxf(s7, 0.f); \
          } \
          float* dp = dest + (size_t)row2 * DIM + 8 * cg; \
          *(float4*)dp = make_float4(s0, s1, s2, s3); \
          *(float4*)(dp + 4) = make_float4(s4, s5, s6, s7); } }

__global__ void k_ngemm(const float* A, const int* gidx, const float* Bw,
                        const float* bias, float* dest, int mode) {
    __shared__ float Bsn[KC * DIM];
    __shared__ float Atsn[KC * NATS];
    __shared__ int s_row[NT];

    int tid = threadIdx.x;
    int base = blockIdx.x * NT;

    if (tid < NT) {
        int r = base + tid;
        int rr = (r < N_NODES) ? r : (N_NODES - 1);
        s_row[tid] = gidx ? gidx[rr] : rr;
    }
    __syncthreads();

    int cg = tid & 15;
    int rg = tid >> 4;
    int arow = tid & 63;
    int aq = tid >> 6;
    DECL_ACC32

    for (int kc = 0; kc < NCHUNK; kc++) {
        for (int i = 0; i < 4; i++) {
            int idx = i * 256 + tid;
            ((float4*)Bsn)[idx] = ((const float4*)(Bw + kc * KC * DIM))[idx];
        }
        {
            const float* hp = A + (size_t)s_row[arow] * DIM + kc * KC;
            float4 v0 = *(const float4*)(hp + 4 * aq);
            float4 v1 = *(const float4*)(hp + 16 + 4 * aq);
            Atsn[(4 * aq + 0) * NATS + arow] = v0.x;
            Atsn[(4 * aq + 1) * NATS + arow] = v0.y;
            Atsn[(4 * aq + 2) * NATS + arow] = v0.z;
            Atsn[(4 * aq + 3) * NATS + arow] = v0.w;
            Atsn[(16 + 4 * aq + 0) * NATS + arow] = v1.x;
            Atsn[(16 + 4 * aq + 1) * NATS + arow] = v1.y;
            Atsn[(16 + 4 * aq + 2) * NATS + arow] = v1.z;
            Atsn[(16 + 4 * aq + 3) * NATS + arow] = v1.w;
        }
        __syncthreads();

        for (int k = 0; k < KC; k++) {
            float4 av  = *(const float4*)&Atsn[k * NATS + 4 * rg];
            float4 bv0 = *(const float4*)&Bsn[k * DIM + 8 * cg];
            float4 bv1 = *(const float4*)&Bsn[k * DIM + 8 * cg + 4];
            float a0 = av.x, a1 = av.y, a2 = av.z, a3 = av.w;
            float b0 = bv0.x, b1 = bv0.y, b2 = bv0.z, b3 = bv0.w;
            float b4 = bv1.x, b5 = bv1.y, b6 = bv1.z, b7 = bv1.w;
            ROWFMA(0) ROWFMA(1) ROWFMA(2) ROWFMA(3)
        }
        __syncthreads();
    }

    float4 bv0 = *(const float4*)(bias + 8 * cg);
    float4 bv1 = *(const float4*)(bias + 8 * cg + 4);
    float bx0 = bv0.x, bx1 = bv0.y, bx2 = bv0.z, bx3 = bv0.w;
    float bx4 = bv1.x, bx5 = bv1.y, bx6 = bv1.z, bx7 = bv1.w;

    NROWOUT(0) NROWOUT(1) NROWOUT(2) NROWOUT(3)
}

// ---------------- launch ----------------
extern "C" void kernel_launch(void* const* d_in, const int* in_sizes, int n_in,
                              void* d_out, int out_size) {
    const int*   x          = (const int*)d_in[0];
    const int*   edge_index = (const int*)d_in[1];
    const int*   edge_type  = (const int*)d_in[2];
    const float* query_emb  = (const float*)d_in[3];
    // d_in[4] = x_batch (unused by reference)
    const int*   edge_batch = (const int*)d_in[5];
    const float* embed_w    = (const float*)d_in[6];
    const float* ilw        = (const float*)d_in[7];
    const float* ilb        = (const float*)d_in[8];
    const float* qpw        = (const float*)d_in[9];
    const float* qpb        = (const float*)d_in[10];
    const float* bases      = (const float*)d_in[11];
    const float* comp       = (const float*)d_in[12];
    const float* rootw      = (const float*)d_in[13];
    const float* lbias      = (const float*)d_in[14];
    const float* relattn    = (const float*)d_in[15];
    float* out = (float*)d_out;

    const int* src = edge_index;
    const int* dst = edge_index + N_EDGES;

    const int NODEB  = (N_NODES + 255) / 256;
    const int NDB    = (N_NODES * DIM + 255) / 256;
    const int EBLK   = (N_EDGES + 255) / 256;
    const int PBLK   = (PERM_SZ + 255) / 256;
    const int ETILES = PERM_SZ / ET;                   // 6300
    const int NTILES = (N_NODES + NT - 1) / NT;        // 782

    float* ha = nullptr; float* hb = nullptr;
    cudaGetSymbolAddress((void**)&ha, g_ha);
    cudaGetSymbolAddress((void**)&hb, g_hb);

    // launch #4 = hinit k_ngemm (ncu capture slot)
    k_qproj<<<NQ, DIM>>>(query_emb, qpw, qpb);
    k_degclr<<<NODEB, 256>>>();
    k_permclr<<<PBLK, 256>>>();
    k_ngemm<<<NTILES, 256>>>(embed_w, x, ilw, ilb, ha, 0);
    k_deghist<<<EBLK, 256>>>(dst);
    k_relhist<<<EBLK, 256>>>(edge_type);
    k_reloff<<<1, 32>>>();
    k_scatter_rel<<<EBLK, 256>>>(edge_type);
    k_deginv<<<NODEB, 256>>>();

    float* cur = ha;
    float* nxt = hb;
    for (int l = 0; l < NLAYERS; l++) {
        k_relW<<<NREL, 256>>>(bases + (size_t)l * NB * DIM * DIM,
                              comp + (size_t)l * NREL * NB);
        k_qatt<<<NQ, 64>>>(relattn + (size_t)l * NREL * DIM);
        k_att<<<EBLK, 256>>>(edge_batch, edge_type);
        k_aggclr<<<NDB, 256>>>();
        k_emsg<<<ETILES, 256>>>(cur, src, dst);
        float* dest = (l == NLAYERS - 1) ? out : nxt;
        int mode = (l == NLAYERS - 1) ? 2 : 1;
        k_ngemm<<<NTILES, 256>>>(cur, nullptr, rootw + (size_t)l * DIM * DIM,
                                 lbias + (size_t)l * DIM, dest, mode);
        float* t = cur; cur = nxt; nxt = t;
    }
}